// round 2
// baseline (speedup 1.0000x reference)
#include <cuda_runtime.h>
#include <math.h>

// Problem constants (this shape variant)
#define Hh    64
#define Ee    64
#define GATES 256   // 4*H
#define KDIM  128   // E + H (concat x;h)
#define OBS_  20
#define MB    64    // batch rows per block
#define NT    256   // threads per block

// Shared memory layout (in floats)
#define OFF_W     0                        // [128][256] k-major concat(Wih;Whh)^T
#define OFF_XH    (OFF_W + KDIM*GATES)     // [128][64]  rows 0..63 = x, 64..127 = h
#define OFF_BIAS  (OFF_XH + KDIM*MB)       // [256]
#define OFF_WE    (OFF_BIAS + GATES)       // [2][64]  sWe[p*64+k] = W_emb[k][p]
#define OFF_BE    (OFF_WE + 2*Ee)          // [64]
#define OFF_WFC   (OFF_BE + Hh)            // [2][64]
#define OFF_BFC   (OFF_WFC + 2*Hh)         // [2] (+2 pad)
#define OFF_OBS   (OFF_BFC + 4)            // [OBS][2][64]
#define OFF_PRED  (OFF_OBS + OBS_*2*MB)    // [2][64]
#define SMEM_FLOATS (OFF_PRED + 2*MB)
#define SMEM_BYTES  (SMEM_FLOATS * 4)

__device__ __forceinline__ float sigf(float x) {
    // robust: x->-inf => exp->inf => 0 ; x->+inf => exp->0 => 1
    return 1.0f / (1.0f + __expf(-x));
}
__device__ __forceinline__ float tanh_(float x) {
    float a = fabsf(x);
    float e = __expf(2.0f * a);            // may be +inf, fine
    float t = 1.0f - 2.0f / (e + 1.0f);    // tanh(|x|)
    return copysignf(t, x);
}

__global__ void __launch_bounds__(NT, 1)
vanilla_lstm_kernel(const float* __restrict__ obs,
                    const float* __restrict__ W_emb,  const float* __restrict__ b_emb,
                    const float* __restrict__ Wih_e,  const float* __restrict__ Whh_e,
                    const float* __restrict__ bih_e,  const float* __restrict__ bhh_e,
                    const float* __restrict__ Wih_d,  const float* __restrict__ Whh_d,
                    const float* __restrict__ bih_d,  const float* __restrict__ bhh_d,
                    const float* __restrict__ W_fc,   const float* __restrict__ b_fc,
                    float* __restrict__ out, int pred_len)
{
    extern __shared__ float sm[];
    float* sW    = sm + OFF_W;
    float* sXH   = sm + OFF_XH;
    float* sBias = sm + OFF_BIAS;
    float* sWe   = sm + OFF_WE;
    float* sBe   = sm + OFF_BE;
    float* sWfc  = sm + OFF_WFC;
    float* sBfc  = sm + OFF_BFC;
    float* sObs  = sm + OFF_OBS;
    float* sPred = sm + OFF_PRED;

    const int tid = threadIdx.x;
    const int tx  = tid & 15;    // batch group (4 per thread)
    const int ty  = tid >> 4;    // hidden group (4 per thread)
    const int b0  = blockIdx.x * MB;

    // ---- stage small params ----
    if (tid < 2 * Ee) {
        int p = tid >> 6, k = tid & 63;
        sWe[tid] = W_emb[k * 2 + p];       // transpose to [p][k]
    }
    if (tid < Hh)  sBe[tid]  = b_emb[tid];
    if (tid < 2*Hh) sWfc[tid] = W_fc[tid]; // [p][k] row-major already
    if (tid < 2)   sBfc[tid] = b_fc[tid];

    // obs cache: sObs[(t*2+p)*64 + b] = obs[(b0+b)*40 + t*2+p]  (coalesced read)
    for (int i = tid; i < MB * OBS_ * 2; i += NT) {
        int b = i / (OBS_ * 2);
        int r = i % (OBS_ * 2);
        sObs[r * MB + b] = obs[(size_t)(b0 + b) * (OBS_ * 2) + r];
    }
    // zero h-part of XH
    for (int i = tid; i < Hh * MB; i += NT) sXH[Ee * MB + i] = 0.0f;

    // ---- stage encoder weights: sW[k][g] = Wih_e[g][k] ; sW[64+k][g] = Whh_e[g][k] ----
    for (int i = tid; i < GATES * Ee; i += NT) {
        int g = i >> 6, k = i & 63;
        sW[k * GATES + g]        = Wih_e[i];
        sW[(64 + k) * GATES + g] = Whh_e[i];
    }
    for (int g = tid; g < GATES; g += NT) sBias[g] = bih_e[g] + bhh_e[g];
    __syncthreads();

    // persistent cell state: c[hidden 0..3][batch 0..3]
    float c[4][4];
    #pragma unroll
    for (int h = 0; h < 4; h++)
        #pragma unroll
        for (int b = 0; b < 4; b++) c[h][b] = 0.0f;

    // ---- embedding: src is [p][64] (p0 row then p1 row) -> XH rows 0..63 ----
    auto embed = [&](const float* src) {
        int col = tid & 63;
        int ks  = (tid >> 6) << 4;     // 16 k-values per thread
        float p0 = src[col], p1 = src[MB + col];
        #pragma unroll
        for (int kk = 0; kk < 16; kk++) {
            int k = ks + kk;
            float v = fmaf(p0, sWe[k], fmaf(p1, sWe[Ee + k], sBe[k]));
            sXH[k * MB + col] = fmaxf(v, 0.0f);
        }
    };

    // ---- one LSTM step: gates = XH^T-GEMM, then elementwise update ----
    auto lstm_step = [&]() {
        float acc[4][4][4];   // [gate i/f/g/o][hidden][batch]
        #pragma unroll
        for (int g = 0; g < 4; g++)
            #pragma unroll
            for (int h = 0; h < 4; h++) {
                float bv = sBias[g * 64 + ty * 4 + h];
                #pragma unroll
                for (int b = 0; b < 4; b++) acc[g][h][b] = bv;
            }

        #pragma unroll 4
        for (int k = 0; k < KDIM; k++) {
            float4 xv = *(const float4*)(sXH + k * MB + tx * 4);
            const float* xp = &xv.x;
            #pragma unroll
            for (int g = 0; g < 4; g++) {
                float4 wv = *(const float4*)(sW + k * GATES + g * 64 + ty * 4);
                const float* wp = &wv.x;
                #pragma unroll
                for (int h = 0; h < 4; h++)
                    #pragma unroll
                    for (int b = 0; b < 4; b++)
                        acc[g][h][b] = fmaf(wp[h], xp[b], acc[g][h][b]);
            }
        }
        __syncthreads();   // all XH reads complete before h overwrite

        #pragma unroll
        for (int h = 0; h < 4; h++) {
            float4 hv;
            float* hvp = &hv.x;
            #pragma unroll
            for (int b = 0; b < 4; b++) {
                float ig = sigf(acc[0][h][b]);
                float fg = sigf(acc[1][h][b]);
                float gg = tanh_(acc[2][h][b]);
                float og = sigf(acc[3][h][b]);
                float cn = fmaf(fg, c[h][b], ig * gg);
                c[h][b]  = cn;
                hvp[b]   = og * tanh_(cn);
            }
            *(float4*)(sXH + (Ee + ty * 4 + h) * MB + tx * 4) = hv;
        }
        __syncthreads();
    };

    // ================= encoder =================
    for (int t = 0; t < OBS_; t++) {
        embed(sObs + t * (2 * MB));
        __syncthreads();
        lstm_step();
    }

    // ---- swap to decoder weights (XH x-part already = emb(obs[:, -1])) ----
    for (int i = tid; i < GATES * Ee; i += NT) {
        int g = i >> 6, k = i & 63;
        sW[k * GATES + g]        = Wih_d[i];
        sW[(64 + k) * GATES + g] = Whh_d[i];
    }
    for (int g = tid; g < GATES; g += NT) sBias[g] = bih_d[g] + bhh_d[g];
    __syncthreads();

    // ================= decoder =================
    for (int t = 0; t < pred_len; t++) {
        lstm_step();   // ends with syncthreads, h in XH rows 64..127

        if (tid < MB) {
            int col = tid;
            float p0 = sBfc[0], p1 = sBfc[1];
            #pragma unroll
            for (int k = 0; k < Hh; k++) {
                float hv = sXH[(Ee + k) * MB + col];
                p0 = fmaf(hv, sWfc[k],      p0);
                p1 = fmaf(hv, sWfc[Hh + k], p1);
            }
            size_t o = ((size_t)(b0 + col) * pred_len + t) * 2;
            out[o]     = p0;
            out[o + 1] = p1;
            sPred[col]      = p0;
            sPred[MB + col] = p1;
        }
        __syncthreads();
        embed(sPred);       // next decoder input
        __syncthreads();
    }
}

extern "C" void kernel_launch(void* const* d_in, const int* in_sizes, int n_in,
                              void* d_out, int out_size)
{
    const float* obs   = (const float*)d_in[0];
    const float* W_emb = (const float*)d_in[1];
    const float* b_emb = (const float*)d_in[2];
    const float* Wih_e = (const float*)d_in[3];
    const float* Whh_e = (const float*)d_in[4];
    const float* bih_e = (const float*)d_in[5];
    const float* bhh_e = (const float*)d_in[6];
    const float* Wih_d = (const float*)d_in[7];
    const float* Whh_d = (const float*)d_in[8];
    const float* bih_d = (const float*)d_in[9];
    const float* bhh_d = (const float*)d_in[10];
    const float* W_fc  = (const float*)d_in[11];
    const float* b_fc  = (const float*)d_in[12];
    float* out = (float*)d_out;

    int B = in_sizes[0] / (OBS_ * 2);
    int pred_len = out_size / (B * 2);

    cudaFuncSetAttribute(vanilla_lstm_kernel,
                         cudaFuncAttributeMaxDynamicSharedMemorySize, SMEM_BYTES);

    int grid = B / MB;
    vanilla_lstm_kernel<<<grid, NT, SMEM_BYTES>>>(
        obs, W_emb, b_emb, Wih_e, Whh_e, bih_e, bhh_e,
        Wih_d, Whh_d, bih_d, bhh_d, W_fc, b_fc, out, pred_len);
}

// round 3
// speedup vs baseline: 1.0491x; 1.0491x over previous
#include <cuda_runtime.h>
#include <math.h>

// Problem constants (this shape variant)
#define Hh    64
#define Ee    64
#define GATES 256   // 4*H
#define KDIM  128   // E + H (concat x;h)
#define OBS_  20
#define MB    64    // batch rows per block
#define NT    256   // threads per block

// Shared memory layout (in floats)
#define OFF_W     0                        // [128][256] k-major concat(Wih;Whh)^T
#define OFF_XH    (OFF_W + KDIM*GATES)     // [128][64]  rows 0..63 = x, 64..127 = h
#define OFF_BIAS  (OFF_XH + KDIM*MB)       // [256]
#define OFF_WE    (OFF_BIAS + GATES)       // [2][64]
#define OFF_BE    (OFF_WE + 2*Ee)          // [64]
#define OFF_WFC   (OFF_BE + Hh)            // [2][64]
#define OFF_BFC   (OFF_WFC + 2*Hh)         // [2] (+2 pad)
#define OFF_OBS   (OFF_BFC + 4)            // [OBS][2][64]
#define OFF_PRED  (OFF_OBS + OBS_*2*MB)    // [2][64]
#define SMEM_FLOATS (OFF_PRED + 2*MB)
#define SMEM_BYTES  (SMEM_FLOATS * 4)

// Packed fp32x2 FMA (Blackwell sm_103a; ptxas never emits FFMA2 from C++)
#define FMA_F32X2(d, a, b, c_) \
    asm("fma.rn.f32x2 %0, %1, %2, %3;" : "=l"(d) : "l"(a), "l"(b), "l"(c_))
#define PACK_DUP_F32X2(out, v) \
    asm("mov.b64 %0, {%1, %1};" : "=l"(out) : "r"(v))
#define UNPACK_F32X2_(lo, hi, in) \
    asm("mov.b64 {%0, %1}, %2;" : "=r"(lo), "=r"(hi) : "l"(in))

__device__ __forceinline__ float sigf(float x) {
    return 1.0f / (1.0f + __expf(-x));
}
__device__ __forceinline__ float tanh_(float x) {
    float a = fabsf(x);
    float e = __expf(2.0f * a);
    float t = 1.0f - 2.0f / (e + 1.0f);
    return copysignf(t, x);
}

__global__ void __launch_bounds__(NT, 1)
vanilla_lstm_kernel(const float* __restrict__ obs,
                    const float* __restrict__ W_emb,  const float* __restrict__ b_emb,
                    const float* __restrict__ Wih_e,  const float* __restrict__ Whh_e,
                    const float* __restrict__ bih_e,  const float* __restrict__ bhh_e,
                    const float* __restrict__ Wih_d,  const float* __restrict__ Whh_d,
                    const float* __restrict__ bih_d,  const float* __restrict__ bhh_d,
                    const float* __restrict__ W_fc,   const float* __restrict__ b_fc,
                    float* __restrict__ out, int pred_len)
{
    extern __shared__ float sm[];
    float* sW    = sm + OFF_W;
    float* sXH   = sm + OFF_XH;
    float* sBias = sm + OFF_BIAS;
    float* sWe   = sm + OFF_WE;
    float* sBe   = sm + OFF_BE;
    float* sWfc  = sm + OFF_WFC;
    float* sBfc  = sm + OFF_BFC;
    float* sObs  = sm + OFF_OBS;
    float* sPred = sm + OFF_PRED;

    const int tid = threadIdx.x;
    const int tx  = tid & 15;    // batch group (4 per thread)
    const int ty  = tid >> 4;    // hidden group (4 per thread)
    const int b0  = blockIdx.x * MB;

    // ---- stage small params ----
    if (tid < 2 * Ee) {
        int p = tid >> 6, k = tid & 63;
        sWe[tid] = W_emb[k * 2 + p];       // transpose to [p][k]
    }
    if (tid < Hh)   sBe[tid]  = b_emb[tid];
    if (tid < 2*Hh) sWfc[tid] = W_fc[tid];
    if (tid < 2)    sBfc[tid] = b_fc[tid];

    // obs cache (coalesced read): sObs[(t*2+p)*64 + b]
    for (int i = tid; i < MB * OBS_ * 2; i += NT) {
        int b = i / (OBS_ * 2);
        int r = i % (OBS_ * 2);
        sObs[r * MB + b] = obs[(size_t)(b0 + b) * (OBS_ * 2) + r];
    }
    // zero h-part of XH
    for (int i = tid; i < Hh * MB; i += NT) sXH[Ee * MB + i] = 0.0f;

    // ---- stage encoder weights: sW[k][g] = Wih_e[g][k] ; sW[64+k][g] = Whh_e[g][k]
    for (int i = tid; i < GATES * Ee; i += NT) {
        int g = i >> 6, k = i & 63;
        sW[k * GATES + g]        = Wih_e[i];
        sW[(64 + k) * GATES + g] = Whh_e[i];
    }
    for (int g = tid; g < GATES; g += NT) sBias[g] = bih_e[g] + bhh_e[g];
    __syncthreads();

    // persistent cell state
    float c[4][4];
    #pragma unroll
    for (int h = 0; h < 4; h++)
        #pragma unroll
        for (int b = 0; b < 4; b++) c[h][b] = 0.0f;

    // ---- embedding: src is [p][64] -> XH rows 0..63 ----
    auto embed = [&](const float* src) {
        int col = tid & 63;
        int ks  = (tid >> 6) << 4;
        float p0 = src[col], p1 = src[MB + col];
        #pragma unroll
        for (int kk = 0; kk < 16; kk++) {
            int k = ks + kk;
            float v = fmaf(p0, sWe[k], fmaf(p1, sWe[Ee + k], sBe[k]));
            sXH[k * MB + col] = fmaxf(v, 0.0f);
        }
    };

    // ---- one LSTM step: packed-f32x2 GEMM, then elementwise update ----
    auto lstm_step = [&]() {
        // acc[gate][hidden-pair][batch]; each f32x2 holds (h=hp*2, h=hp*2+1)
        unsigned long long acc[4][2][4];
        #pragma unroll
        for (int g = 0; g < 4; g++)
            #pragma unroll
            for (int hp = 0; hp < 2; hp++) {
                const unsigned long long bp =
                    *(const unsigned long long*)(sBias + g * 64 + ty * 4 + hp * 2);
                #pragma unroll
                for (int b = 0; b < 4; b++) acc[g][hp][b] = bp;
            }

        #pragma unroll 4
        for (int k = 0; k < KDIM; k++) {
            float4 xv = *(const float4*)(sXH + k * MB + tx * 4);
            unsigned long long xb[4];
            PACK_DUP_F32X2(xb[0], __float_as_uint(xv.x));
            PACK_DUP_F32X2(xb[1], __float_as_uint(xv.y));
            PACK_DUP_F32X2(xb[2], __float_as_uint(xv.z));
            PACK_DUP_F32X2(xb[3], __float_as_uint(xv.w));
            #pragma unroll
            for (int g = 0; g < 4; g++) {
                float4 wv = *(const float4*)(sW + k * GATES + g * 64 + ty * 4);
                unsigned long long wp[2];
                wp[0] = *(unsigned long long*)&wv.x;   // {w0, w1}
                wp[1] = *(unsigned long long*)&wv.z;   // {w2, w3}
                #pragma unroll
                for (int hp = 0; hp < 2; hp++)
                    #pragma unroll
                    for (int b = 0; b < 4; b++)
                        FMA_F32X2(acc[g][hp][b], wp[hp], xb[b], acc[g][hp][b]);
            }
        }
        __syncthreads();   // all XH reads done before h overwrite

        float hv[4][4];    // [h][b]
        #pragma unroll
        for (int hp = 0; hp < 2; hp++)
            #pragma unroll
            for (int b = 0; b < 4; b++) {
                unsigned int i0u, i1u, f0u, f1u, g0u, g1u, o0u, o1u;
                UNPACK_F32X2_(i0u, i1u, acc[0][hp][b]);
                UNPACK_F32X2_(f0u, f1u, acc[1][hp][b]);
                UNPACK_F32X2_(g0u, g1u, acc[2][hp][b]);
                UNPACK_F32X2_(o0u, o1u, acc[3][hp][b]);
                {
                    int h = hp * 2;
                    float ig = sigf(__uint_as_float(i0u));
                    float fg = sigf(__uint_as_float(f0u));
                    float gg = tanh_(__uint_as_float(g0u));
                    float og = sigf(__uint_as_float(o0u));
                    float cn = fmaf(fg, c[h][b], ig * gg);
                    c[h][b] = cn;
                    hv[h][b] = og * tanh_(cn);
                }
                {
                    int h = hp * 2 + 1;
                    float ig = sigf(__uint_as_float(i1u));
                    float fg = sigf(__uint_as_float(f1u));
                    float gg = tanh_(__uint_as_float(g1u));
                    float og = sigf(__uint_as_float(o1u));
                    float cn = fmaf(fg, c[h][b], ig * gg);
                    c[h][b] = cn;
                    hv[h][b] = og * tanh_(cn);
                }
            }

        #pragma unroll
        for (int h = 0; h < 4; h++) {
            float4 v = make_float4(hv[h][0], hv[h][1], hv[h][2], hv[h][3]);
            *(float4*)(sXH + (Ee + ty * 4 + h) * MB + tx * 4) = v;
        }
        __syncthreads();
    };

    // ================= encoder =================
    for (int t = 0; t < OBS_; t++) {
        embed(sObs + t * (2 * MB));
        __syncthreads();
        lstm_step();
    }

    // ---- swap to decoder weights ----
    for (int i = tid; i < GATES * Ee; i += NT) {
        int g = i >> 6, k = i & 63;
        sW[k * GATES + g]        = Wih_d[i];
        sW[(64 + k) * GATES + g] = Whh_d[i];
    }
    for (int g = tid; g < GATES; g += NT) sBias[g] = bih_d[g] + bhh_d[g];
    __syncthreads();

    // ================= decoder =================
    for (int t = 0; t < pred_len; t++) {
        lstm_step();

        if (tid < MB) {
            int col = tid;
            float p0 = sBfc[0], p1 = sBfc[1];
            #pragma unroll
            for (int k = 0; k < Hh; k++) {
                float h = sXH[(Ee + k) * MB + col];
                p0 = fmaf(h, sWfc[k],      p0);
                p1 = fmaf(h, sWfc[Hh + k], p1);
            }
            size_t o = ((size_t)(b0 + col) * pred_len + t) * 2;
            out[o]     = p0;
            out[o + 1] = p1;
            sPred[col]      = p0;
            sPred[MB + col] = p1;
        }
        __syncthreads();
        embed(sPred);
        __syncthreads();
    }
}

extern "C" void kernel_launch(void* const* d_in, const int* in_sizes, int n_in,
                              void* d_out, int out_size)
{
    const float* obs   = (const float*)d_in[0];
    const float* W_emb = (const float*)d_in[1];
    const float* b_emb = (const float*)d_in[2];
    const float* Wih_e = (const float*)d_in[3];
    const float* Whh_e = (const float*)d_in[4];
    const float* bih_e = (const float*)d_in[5];
    const float* bhh_e = (const float*)d_in[6];
    const float* Wih_d = (const float*)d_in[7];
    const float* Whh_d = (const float*)d_in[8];
    const float* bih_d = (const float*)d_in[9];
    const float* bhh_d = (const float*)d_in[10];
    const float* W_fc  = (const float*)d_in[11];
    const float* b_fc  = (const float*)d_in[12];
    float* out = (float*)d_out;

    int B = in_sizes[0] / (OBS_ * 2);
    int pred_len = out_size / (B * 2);

    cudaFuncSetAttribute(vanilla_lstm_kernel,
                         cudaFuncAttributeMaxDynamicSharedMemorySize, SMEM_BYTES);

    int grid = B / MB;
    vanilla_lstm_kernel<<<grid, NT, SMEM_BYTES>>>(
        obs, W_emb, b_emb, Wih_e, Whh_e, bih_e, bhh_e,
        Wih_d, Whh_d, bih_d, bhh_d, W_fc, b_fc, out, pred_len);
}

// round 4
// speedup vs baseline: 1.1821x; 1.1268x over previous
#include <cuda_runtime.h>
#include <math.h>

// Problem constants (this shape variant)
#define Hh    64
#define Ee    64
#define GATES 256   // 4*H
#define KDIM  128   // E + H (concat x;h)
#define OBS_  20
#define MB    64    // batch rows per block
#define NT    512   // threads per block (16 warps)

// Shared memory layout (in floats)
// sW layout: sW[k*256 + ty*8 + g*2 + d] = W[g*64 + ty*2 + d][k]
#define OFF_W     0                        // [128][256] permuted gate-pair layout
#define OFF_XH    (OFF_W + KDIM*GATES)     // [128][64] rows 0..63 = x, 64..127 = h
#define OFF_BIAS  (OFF_XH + KDIM*MB)       // [256] permuted: [ty][g][d]
#define OFF_WE    (OFF_BIAS + GATES)       // [2][64]
#define OFF_BE    (OFF_WE + 2*Ee)          // [64]
#define OFF_WFC   (OFF_BE + Hh)            // [2][64]
#define OFF_BFC   (OFF_WFC + 2*Hh)         // [2] (+2 pad)
#define OFF_OBS   (OFF_BFC + 4)            // [OBS][2][64]
#define OFF_PRED  (OFF_OBS + OBS_*2*MB)    // [2][64]
#define SMEM_FLOATS (OFF_PRED + 2*MB)
#define SMEM_BYTES  (SMEM_FLOATS * 4)

// Packed fp32x2 FMA (Blackwell; ptxas never emits FFMA2 from C++)
#define FMA_F32X2(d, a, b, c_) \
    asm("fma.rn.f32x2 %0, %1, %2, %3;" : "=l"(d) : "l"(a), "l"(b), "l"(c_))
#define PACK_DUP_F32X2(out, v) \
    asm("mov.b64 %0, {%1, %1};" : "=l"(out) : "r"(v))
#define UNPACK_F32X2_(lo, hi, in) \
    asm("mov.b64 {%0, %1}, %2;" : "=r"(lo), "=r"(hi) : "l"(in))

__device__ __forceinline__ float sigf(float x) {
    return 1.0f / (1.0f + __expf(-x));
}
__device__ __forceinline__ float tanh_(float x) {
    float a = fabsf(x);
    float e = __expf(2.0f * a);
    float t = 1.0f - 2.0f / (e + 1.0f);
    return copysignf(t, x);
}

__global__ void __launch_bounds__(NT, 1)
vanilla_lstm_kernel(const float* __restrict__ obs,
                    const float* __restrict__ W_emb,  const float* __restrict__ b_emb,
                    const float* __restrict__ Wih_e,  const float* __restrict__ Whh_e,
                    const float* __restrict__ bih_e,  const float* __restrict__ bhh_e,
                    const float* __restrict__ Wih_d,  const float* __restrict__ Whh_d,
                    const float* __restrict__ bih_d,  const float* __restrict__ bhh_d,
                    const float* __restrict__ W_fc,   const float* __restrict__ b_fc,
                    float* __restrict__ out, int pred_len)
{
    extern __shared__ float sm[];
    float* sW    = sm + OFF_W;
    float* sXH   = sm + OFF_XH;
    float* sBias = sm + OFF_BIAS;
    float* sWe   = sm + OFF_WE;
    float* sBe   = sm + OFF_BE;
    float* sWfc  = sm + OFF_WFC;
    float* sBfc  = sm + OFF_BFC;
    float* sObs  = sm + OFF_OBS;
    float* sPred = sm + OFF_PRED;

    const int tid = threadIdx.x;
    const int tx  = tid & 15;            // batch group (4 per thread)
    const int ty  = (tid >> 4) & 31;     // hidden pair (2 per thread)
    const int b0  = blockIdx.x * MB;

    // ---- stage small params ----
    if (tid < 2 * Ee) {
        int p = tid >> 6, k = tid & 63;
        sWe[tid] = W_emb[k * 2 + p];       // transpose to [p][k]
    }
    if (tid < Hh)   sBe[tid]  = b_emb[tid];
    if (tid < 2*Hh) sWfc[tid] = W_fc[tid];
    if (tid < 2)    sBfc[tid] = b_fc[tid];

    // obs cache (coalesced read): sObs[(t*2+p)*64 + b]
    for (int i = tid; i < MB * OBS_ * 2; i += NT) {
        int b = i / (OBS_ * 2);
        int r = i % (OBS_ * 2);
        sObs[r * MB + b] = obs[(size_t)(b0 + b) * (OBS_ * 2) + r];
    }
    // zero h-part of XH
    for (int i = tid; i < Hh * MB; i += NT) sXH[Ee * MB + i] = 0.0f;

    // ---- stage weights in permuted gate-pair layout ----
    // row = g*64 + ty*2 + d   ->  sW[k*256 + ty*8 + g*2 + d]
    auto stage_weights = [&](const float* Wih, const float* Whh,
                             const float* bih, const float* bhh) {
        for (int i = tid; i < GATES * Ee; i += NT) {
            int row = i >> 6, k = i & 63;
            int g = row >> 6, hidx = row & 63;
            int ty_ = hidx >> 1, d = hidx & 1;
            int slot = ty_ * 8 + g * 2 + d;
            sW[k * GATES + slot]        = Wih[i];
            sW[(64 + k) * GATES + slot] = Whh[i];
        }
        for (int row = tid; row < GATES; row += NT) {
            int g = row >> 6, hidx = row & 63;
            sBias[(hidx >> 1) * 8 + g * 2 + (hidx & 1)] = bih[row] + bhh[row];
        }
    };
    stage_weights(Wih_e, Whh_e, bih_e, bhh_e);
    __syncthreads();

    // persistent cell state: c[hidden d][batch]
    float c[2][4];
    #pragma unroll
    for (int d = 0; d < 2; d++)
        #pragma unroll
        for (int b = 0; b < 4; b++) c[d][b] = 0.0f;

    // ---- embedding: src is [p][64] -> XH rows 0..63 ----
    auto embed = [&](const float* src) {
        int col = tid & 63;
        int ks  = (tid >> 6) << 3;   // 8 k values per thread, 8 groups
        float p0 = src[col], p1 = src[MB + col];
        #pragma unroll
        for (int kk = 0; kk < 8; kk++) {
            int k = ks + kk;
            float v = fmaf(p0, sWe[k], fmaf(p1, sWe[Ee + k], sBe[k]));
            sXH[k * MB + col] = fmaxf(v, 0.0f);
        }
    };

    // ---- one LSTM step ----
    auto lstm_step = [&]() {
        // acc[gate][batch], each f32x2 holds hidden pair (2*ty, 2*ty+1)
        unsigned long long acc[4][4];
        #pragma unroll
        for (int g = 0; g < 4; g++) {
            unsigned long long bp =
                *(const unsigned long long*)(sBias + ty * 8 + g * 2);
            #pragma unroll
            for (int b = 0; b < 4; b++) acc[g][b] = bp;
        }

        #pragma unroll 4
        for (int k = 0; k < KDIM; k++) {
            float4 xv = *(const float4*)(sXH + k * MB + tx * 4);
            unsigned long long xb[4];
            PACK_DUP_F32X2(xb[0], __float_as_uint(xv.x));
            PACK_DUP_F32X2(xb[1], __float_as_uint(xv.y));
            PACK_DUP_F32X2(xb[2], __float_as_uint(xv.z));
            PACK_DUP_F32X2(xb[3], __float_as_uint(xv.w));

            float4 w01 = *(const float4*)(sW + k * GATES + ty * 8);
            float4 w23 = *(const float4*)(sW + k * GATES + ty * 8 + 4);
            unsigned long long wp[4];
            wp[0] = *(unsigned long long*)&w01.x;
            wp[1] = *(unsigned long long*)&w01.z;
            wp[2] = *(unsigned long long*)&w23.x;
            wp[3] = *(unsigned long long*)&w23.z;

            #pragma unroll
            for (int g = 0; g < 4; g++)
                #pragma unroll
                for (int b = 0; b < 4; b++)
                    FMA_F32X2(acc[g][b], wp[g], xb[b], acc[g][b]);
        }
        __syncthreads();   // all XH reads done before h overwrite

        float hv[2][4];
        #pragma unroll
        for (int b = 0; b < 4; b++) {
            unsigned int i0u, i1u, f0u, f1u, g0u, g1u, o0u, o1u;
            UNPACK_F32X2_(i0u, i1u, acc[0][b]);
            UNPACK_F32X2_(f0u, f1u, acc[1][b]);
            UNPACK_F32X2_(g0u, g1u, acc[2][b]);
            UNPACK_F32X2_(o0u, o1u, acc[3][b]);
            {
                float ig = sigf(__uint_as_float(i0u));
                float fg = sigf(__uint_as_float(f0u));
                float gg = tanh_(__uint_as_float(g0u));
                float og = sigf(__uint_as_float(o0u));
                float cn = fmaf(fg, c[0][b], ig * gg);
                c[0][b] = cn;
                hv[0][b] = og * tanh_(cn);
            }
            {
                float ig = sigf(__uint_as_float(i1u));
                float fg = sigf(__uint_as_float(f1u));
                float gg = tanh_(__uint_as_float(g1u));
                float og = sigf(__uint_as_float(o1u));
                float cn = fmaf(fg, c[1][b], ig * gg);
                c[1][b] = cn;
                hv[1][b] = og * tanh_(cn);
            }
        }

        #pragma unroll
        for (int d = 0; d < 2; d++) {
            float4 v = make_float4(hv[d][0], hv[d][1], hv[d][2], hv[d][3]);
            *(float4*)(sXH + (Ee + ty * 2 + d) * MB + tx * 4) = v;
        }
        __syncthreads();
    };

    // ================= encoder =================
    for (int t = 0; t < OBS_; t++) {
        embed(sObs + t * (2 * MB));
        __syncthreads();
        lstm_step();
    }

    // ---- swap to decoder weights ----
    stage_weights(Wih_d, Whh_d, bih_d, bhh_d);
    __syncthreads();

    // ================= decoder =================
    for (int t = 0; t < pred_len; t++) {
        lstm_step();

        if (tid < MB) {
            int col = tid;
            float p0 = sBfc[0], p1 = sBfc[1];
            #pragma unroll
            for (int k = 0; k < Hh; k++) {
                float h = sXH[(Ee + k) * MB + col];
                p0 = fmaf(h, sWfc[k],      p0);
                p1 = fmaf(h, sWfc[Hh + k], p1);
            }
            size_t o = ((size_t)(b0 + col) * pred_len + t) * 2;
            out[o]     = p0;
            out[o + 1] = p1;
            sPred[col]      = p0;
            sPred[MB + col] = p1;
        }
        __syncthreads();
        embed(sPred);
        __syncthreads();
    }
}

extern "C" void kernel_launch(void* const* d_in, const int* in_sizes, int n_in,
                              void* d_out, int out_size)
{
    const float* obs   = (const float*)d_in[0];
    const float* W_emb = (const float*)d_in[1];
    const float* b_emb = (const float*)d_in[2];
    const float* Wih_e = (const float*)d_in[3];
    const float* Whh_e = (const float*)d_in[4];
    const float* bih_e = (const float*)d_in[5];
    const float* bhh_e = (const float*)d_in[6];
    const float* Wih_d = (const float*)d_in[7];
    const float* Whh_d = (const float*)d_in[8];
    const float* bih_d = (const float*)d_in[9];
    const float* bhh_d = (const float*)d_in[10];
    const float* W_fc  = (const float*)d_in[11];
    const float* b_fc  = (const float*)d_in[12];
    float* out = (float*)d_out;

    int B = in_sizes[0] / (OBS_ * 2);
    int pred_len = out_size / (B * 2);

    cudaFuncSetAttribute(vanilla_lstm_kernel,
                         cudaFuncAttributeMaxDynamicSharedMemorySize, SMEM_BYTES);

    int grid = B / MB;
    vanilla_lstm_kernel<<<grid, NT, SMEM_BYTES>>>(
        obs, W_emb, b_emb, Wih_e, Whh_e, bih_e, bhh_e,
        Wih_d, Whh_d, bih_d, bhh_d, W_fc, b_fc, out, pred_len);
}